// round 1
// baseline (speedup 1.0000x reference)
#include <cuda_runtime.h>
#include <cstdint>

// ---------------------------------------------------------------------------
// GenerativeUpsample: per-batch kth-smallest threshold on pred, prune fea.
//   fea:  [N, 64] f32      d_in[0]
//   pred: [N, 1]  f32      d_in[1]
//   bid:  [N]     i32      d_in[2]  (sorted, values in [0,B))
//   tgt:  [B]     i32      d_in[3]
// out: [N*64] pruned fea, then (if room) [N] keep as 0/1 float.
//
// Method: exact 2-level radix select (16+16 bits) on monotone key of pred.
// ---------------------------------------------------------------------------

#define MAXB 8
#define NBIN 65536

__device__ unsigned g_hist1[MAXB * NBIN];
__device__ unsigned g_hist2[MAXB * NBIN];
__device__ int      g_counts[MAXB];
__device__ unsigned g_selBin[MAXB];
__device__ unsigned g_selRank[MAXB];
__device__ int      g_active[MAXB];
__device__ unsigned g_threshKey[MAXB];

__device__ __forceinline__ unsigned f2key(float f) {
    unsigned u = __float_as_uint(f);
    return (u & 0x80000000u) ? ~u : (u | 0x80000000u);
}

// -------- zero scratch (graph replays require reset every launch) ----------
__global__ void k_zero() {
    int total = 2 * MAXB * NBIN + MAXB;
    for (int i = blockIdx.x * blockDim.x + threadIdx.x; i < total;
         i += gridDim.x * blockDim.x) {
        if (i < MAXB * NBIN)          g_hist1[i] = 0u;
        else if (i < 2 * MAXB * NBIN) g_hist2[i - MAXB * NBIN] = 0u;
        else                          g_counts[i - 2 * MAXB * NBIN] = 0;
    }
}

// -------- pass 1: per-batch counts + top-16-bit histogram ------------------
__global__ void k_hist1(const float* __restrict__ pred,
                        const int* __restrict__ bid, int n) {
    __shared__ int scount[MAXB];
    if (threadIdx.x < MAXB) scount[threadIdx.x] = 0;
    __syncthreads();
    for (int i = blockIdx.x * blockDim.x + threadIdx.x; i < n;
         i += gridDim.x * blockDim.x) {
        int b = bid[i];
        unsigned key = f2key(pred[i]);
        atomicAdd(&g_hist1[b * NBIN + (key >> 16)], 1u);
        atomicAdd(&scount[b], 1);
    }
    __syncthreads();
    if (threadIdx.x < MAXB) atomicAdd(&g_counts[threadIdx.x], scount[threadIdx.x]);
}

// -------- select bin from a 65536-bin histogram ----------------------------
// One block (1024 threads) per batch. Each thread sums 64 bins, thread 0
// does the tiny serial prefix + in-segment walk.
__global__ void k_sel1(const int* __restrict__ tgt) {
    int b = blockIdx.x;
    __shared__ unsigned partial[1024];
    const unsigned* h = &g_hist1[b * NBIN];
    unsigned s = 0;
    int base = threadIdx.x * 64;
    #pragma unroll 4
    for (int j = 0; j < 64; j++) s += h[base + j];
    partial[threadIdx.x] = s;
    __syncthreads();
    if (threadIdx.x == 0) {
        int n = g_counts[b];
        int t = tgt[b];
        if (n <= t) {
            g_active[b] = 0;
            g_selBin[b] = 0xFFFFFFFFu;  // sentinel: matches nothing in pass 2
            g_selRank[b] = 0;
        } else {
            g_active[b] = 1;
            long long rank = (long long)n - t - 1;  // 0-indexed kth
            int seg = 0;
            while (rank >= (long long)partial[seg]) { rank -= partial[seg]; seg++; }
            int j = seg * 64;
            while (rank >= (long long)h[j]) { rank -= h[j]; j++; }
            g_selBin[b] = (unsigned)j;
            g_selRank[b] = (unsigned)rank;
        }
    }
}

// -------- pass 2: low-16-bit histogram of in-bin elements ------------------
__global__ void k_hist2(const float* __restrict__ pred,
                        const int* __restrict__ bid, int n) {
    for (int i = blockIdx.x * blockDim.x + threadIdx.x; i < n;
         i += gridDim.x * blockDim.x) {
        int b = bid[i];
        unsigned key = f2key(pred[i]);
        if ((key >> 16) == g_selBin[b])
            atomicAdd(&g_hist2[b * NBIN + (key & 0xFFFFu)], 1u);
    }
}

// -------- finalize exact threshold key -------------------------------------
__global__ void k_sel2() {
    int b = blockIdx.x;
    __shared__ unsigned partial[1024];
    const unsigned* h = &g_hist2[b * NBIN];
    unsigned s = 0;
    int base = threadIdx.x * 64;
    #pragma unroll 4
    for (int j = 0; j < 64; j++) s += h[base + j];
    partial[threadIdx.x] = s;
    __syncthreads();
    if (threadIdx.x == 0) {
        if (!g_active[b]) {
            g_threshKey[b] = 0u;  // every real float key is > 0 -> keep all
        } else {
            long long rank = (long long)g_selRank[b];
            int seg = 0;
            while (rank >= (long long)partial[seg]) { rank -= partial[seg]; seg++; }
            int j = seg * 64;
            while (rank >= (long long)h[j]) { rank -= h[j]; j++; }
            g_threshKey[b] = (g_selBin[b] << 16) | (unsigned)j;
        }
    }
}

// -------- streaming prune: out = fea * keep, plus keep array ---------------
// One thread per float4 (16 per row). keep recomputed per thread; pred/bid
// loads hit L1 broadcast lines.
__global__ void k_prune(const float4* __restrict__ fea4,
                        const float* __restrict__ pred,
                        const int* __restrict__ bid,
                        float4* __restrict__ out4,
                        float* __restrict__ out_keep,
                        int n, int writeKeep) {
    int gid = blockIdx.x * blockDim.x + threadIdx.x;
    int total = n * 16;
    if (gid >= total) return;
    int row = gid >> 4;
    int b = bid[row];
    unsigned key = f2key(pred[row]);
    float kf = (key > g_threshKey[b]) ? 1.0f : 0.0f;
    float4 v = fea4[gid];
    v.x *= kf; v.y *= kf; v.z *= kf; v.w *= kf;
    out4[gid] = v;
    if (writeKeep && ((gid & 15) == 0)) out_keep[row] = kf;
}

extern "C" void kernel_launch(void* const* d_in, const int* in_sizes, int n_in,
                              void* d_out, int out_size) {
    const float* fea  = (const float*)d_in[0];
    const float* pred = (const float*)d_in[1];
    const int*   bid  = (const int*)d_in[2];
    const int*   tgt  = (const int*)d_in[3];
    const int n = in_sizes[1];      // N points
    const int C = in_sizes[0] / n;  // 64

    float* out_fea  = (float*)d_out;
    int writeKeep = (out_size >= n * C + n) ? 1 : 0;
    float* out_keep = out_fea + (size_t)n * C;

    k_zero<<<2048, 512>>>();
    k_hist1<<<2048, 256>>>(pred, bid, n);
    k_sel1<<<MAXB, 1024>>>(tgt);
    k_hist2<<<2048, 256>>>(pred, bid, n);
    k_sel2<<<MAXB, 1024>>>();
    int total4 = n * (C / 4);
    k_prune<<<(total4 + 255) / 256, 256>>>((const float4*)fea, pred, bid,
                                           (float4*)d_out, out_keep, n, writeKeep);
}

// round 4
// speedup vs baseline: 1.3170x; 1.3170x over previous
#include <cuda_runtime.h>
#include <cstdint>

// ---------------------------------------------------------------------------
// GenerativeUpsample: per-batch kth-smallest threshold on pred, prune fea.
//   fea:  [N, 64] f32      d_in[0]
//   pred: [N, 1]  f32      d_in[1]
//   bid:  [N]     i32      d_in[2]  (sorted, values in [0,B))
//   tgt:  [B]     i32      d_in[3]
// out: [N*64] pruned fea, then (if room) [N] keep as 0/1 float.
//
// Exact 2-level (16+16 bit) radix select on the monotone uint key of pred.
// NOTE: device scratch symbols are NEVER passed as kernel args from host
// (host shadow address is invalid on device) — kernels pick hist via flag.
// ---------------------------------------------------------------------------

#define MAXB 8
#define NBIN 65536
#define NSEG 64          // segments per 65536-bin histogram
#define SEGBINS 1024     // bins per segment

__device__ unsigned g_hist1[MAXB * NBIN];
__device__ unsigned g_hist2[MAXB * NBIN];
__device__ unsigned g_seg[MAXB * NSEG];
__device__ int      g_off[MAXB + 1];
__device__ unsigned g_selBin[MAXB];
__device__ unsigned g_selRank[MAXB];
__device__ int      g_active[MAXB];
__device__ unsigned g_threshKey[MAXB];

__device__ __forceinline__ unsigned f2key(float f) {
    unsigned u = __float_as_uint(f);
    return (u & 0x80000000u) ? ~u : (u | 0x80000000u);
}

// batch id from row index via 7 compares against offsets (bids are sorted)
__device__ __forceinline__ int batch_of(int i, const int* o) {
    int b = 0;
    #pragma unroll
    for (int k = 1; k < MAXB; k++) b += (i >= o[k]);
    return b;
}

// -------- batch boundaries via binary search (bids sorted) -----------------
__global__ void k_bounds(const int* __restrict__ bid, int n) {
    int t = threadIdx.x;
    if (t > MAXB) return;
    if (t == MAXB) { g_off[MAXB] = n; return; }
    int lo = 0, hi = n;
    while (lo < hi) {
        int mid = (lo + hi) >> 1;
        if (bid[mid] < t) lo = mid + 1; else hi = mid;
    }
    g_off[t] = lo;
}

// -------- zero scratch (graph replays need reset every launch) -------------
__global__ void k_zero() {
    int total = 2 * MAXB * NBIN;
    for (int i = blockIdx.x * blockDim.x + threadIdx.x; i < total;
         i += gridDim.x * blockDim.x) {
        if (i < MAXB * NBIN) g_hist1[i] = 0u;
        else                 g_hist2[i - MAXB * NBIN] = 0u;
    }
}

// -------- pass 1: top-16-bit histogram, float4 loads -----------------------
__global__ void k_hist1(const float4* __restrict__ pred4, int n4) {
    __shared__ int soff[MAXB + 1];
    if (threadIdx.x <= MAXB) soff[threadIdx.x] = g_off[threadIdx.x];
    __syncthreads();
    int o[MAXB + 1];
    #pragma unroll
    for (int k = 0; k <= MAXB; k++) o[k] = soff[k];

    for (int i4 = blockIdx.x * blockDim.x + threadIdx.x; i4 < n4;
         i4 += gridDim.x * blockDim.x) {
        float4 p = pred4[i4];
        int base = i4 * 4;
        float pv[4] = {p.x, p.y, p.z, p.w};
        #pragma unroll
        for (int j = 0; j < 4; j++) {
            int b = batch_of(base + j, o);
            atomicAdd(&g_hist1[b * NBIN + (f2key(pv[j]) >> 16)], 1u);
        }
    }
}

// -------- pass 2: low-16-bit histogram of in-selected-bin elements ---------
__global__ void k_hist2(const float4* __restrict__ pred4, int n4) {
    __shared__ int soff[MAXB + 1];
    __shared__ unsigned ssel[MAXB];
    if (threadIdx.x <= MAXB) soff[threadIdx.x] = g_off[threadIdx.x];
    if (threadIdx.x < MAXB)  ssel[threadIdx.x] = g_selBin[threadIdx.x];
    __syncthreads();
    int o[MAXB + 1];
    #pragma unroll
    for (int k = 0; k <= MAXB; k++) o[k] = soff[k];

    for (int i4 = blockIdx.x * blockDim.x + threadIdx.x; i4 < n4;
         i4 += gridDim.x * blockDim.x) {
        float4 p = pred4[i4];
        int base = i4 * 4;
        float pv[4] = {p.x, p.y, p.z, p.w};
        #pragma unroll
        for (int j = 0; j < 4; j++) {
            int b = batch_of(base + j, o);
            unsigned key = f2key(pv[j]);
            if ((key >> 16) == ssel[b])
                atomicAdd(&g_hist2[b * NBIN + (key & 0xFFFFu)], 1u);
        }
    }
}

// -------- coarse segment sums: 8 batches x 64 segs = 512 blocks ------------
// which: 1 -> g_hist1, 2 -> g_hist2 (device symbols not passable from host)
__global__ void k_coarse(int which) {
    const unsigned* hist = (which == 1) ? g_hist1 : g_hist2;
    int b = blockIdx.x >> 6;
    int s = blockIdx.x & 63;
    const uint4* h4 =
        (const uint4*)&hist[b * NBIN + s * SEGBINS];  // 256 uint4 per segment
    uint4 v = h4[threadIdx.x];
    unsigned sum = v.x + v.y + v.z + v.w;
    #pragma unroll
    for (int d = 16; d > 0; d >>= 1) sum += __shfl_down_sync(0xFFFFFFFFu, sum, d);
    __shared__ unsigned ws[8];
    if ((threadIdx.x & 31) == 0) ws[threadIdx.x >> 5] = sum;
    __syncthreads();
    if (threadIdx.x == 0) {
        unsigned t = 0;
        #pragma unroll
        for (int w = 0; w < 8; w++) t += ws[w];
        g_seg[b * NSEG + s] = t;
    }
}

// -------- walk: find exact bin + residual rank. 8 tiny blocks. -------------
__global__ void k_walk(int level, const int* __restrict__ tgt) {
    const unsigned* hist = (level == 1) ? g_hist1 : g_hist2;
    int b = blockIdx.x;
    __shared__ unsigned ssum[256];
    __shared__ int sact;
    __shared__ unsigned srank, ssegi;

    if (threadIdx.x == 0) {
        long long rank;
        int act;
        if (level == 1) {
            int n = g_off[b + 1] - g_off[b];
            int t = tgt[b];
            act = (n > t);
            rank = (long long)n - t - 1;
        } else {
            act = g_active[b];
            rank = (long long)g_selRank[b];
        }
        if (act) {
            const unsigned* seg = &g_seg[b * NSEG];
            int s = 0;
            while (rank >= (long long)seg[s]) { rank -= seg[s]; s++; }
            ssegi = (unsigned)s;
            srank = (unsigned)rank;
        }
        sact = act;
    }
    __syncthreads();
    if (!sact) {
        if (threadIdx.x == 0) {
            if (level == 1) {
                g_active[b] = 0;
                g_selBin[b] = 0xFFFFFFFFu;  // matches nothing in pass 2
                g_selRank[b] = 0;
            } else {
                g_threshKey[b] = 0u;  // every real key > 0 -> keep all
            }
        }
        return;
    }
    // sum 4 bins per thread within the selected segment
    const uint4* h4 = (const uint4*)&hist[b * NBIN + ssegi * SEGBINS];
    uint4 v = h4[threadIdx.x];
    ssum[threadIdx.x] = v.x + v.y + v.z + v.w;
    __syncthreads();
    if (threadIdx.x == 0) {
        long long rank = (long long)srank;
        int tt = 0;
        while (rank >= (long long)ssum[tt]) { rank -= ssum[tt]; tt++; }
        const unsigned* hb = &hist[b * NBIN + ssegi * SEGBINS + tt * 4];
        int j = 0;
        while (rank >= (long long)hb[j]) { rank -= hb[j]; j++; }
        unsigned bin = ssegi * SEGBINS + tt * 4 + j;
        if (level == 1) {
            g_selBin[b] = bin;
            g_selRank[b] = (unsigned)rank;
            g_active[b] = 1;
        } else {
            g_threshKey[b] = (g_selBin[b] << 16) | bin;
        }
    }
}

// -------- streaming prune: out = fea * keep, plus keep array ---------------
__global__ void k_prune(const float4* __restrict__ fea4,
                        const float* __restrict__ pred,
                        float4* __restrict__ out4,
                        float* __restrict__ out_keep,
                        int total4, int writeKeep) {
    __shared__ unsigned sthr[MAXB];
    __shared__ int soff[MAXB + 1];
    if (threadIdx.x < MAXB) sthr[threadIdx.x] = g_threshKey[threadIdx.x];
    if (threadIdx.x >= 32 && threadIdx.x <= 32 + MAXB)
        soff[threadIdx.x - 32] = g_off[threadIdx.x - 32];
    __syncthreads();

    int gid = blockIdx.x * blockDim.x + threadIdx.x;
    if (gid >= total4) return;
    int row = gid >> 4;  // 16 float4 per 64-wide row
    int o[MAXB + 1];
    #pragma unroll
    for (int k = 0; k <= MAXB; k++) o[k] = soff[k];
    int b = batch_of(row, o);
    unsigned key = f2key(pred[row]);
    float kf = (key > sthr[b]) ? 1.0f : 0.0f;
    float4 v = __ldcs(&fea4[gid]);
    v.x *= kf; v.y *= kf; v.z *= kf; v.w *= kf;
    __stcs(&out4[gid], v);
    if (writeKeep && ((gid & 15) == 0)) out_keep[row] = kf;
}

extern "C" void kernel_launch(void* const* d_in, const int* in_sizes, int n_in,
                              void* d_out, int out_size) {
    const float* fea  = (const float*)d_in[0];
    const float* pred = (const float*)d_in[1];
    const int*   bid  = (const int*)d_in[2];
    const int*   tgt  = (const int*)d_in[3];
    const int n = in_sizes[1];      // N points
    const int C = in_sizes[0] / n;  // 64

    float* out_fea  = (float*)d_out;
    int writeKeep = (out_size >= n * C + n) ? 1 : 0;
    float* out_keep = out_fea + (size_t)n * C;

    k_bounds<<<1, 32>>>(bid, n);
    k_zero<<<2048, 512>>>();
    int n4 = n / 4;
    k_hist1<<<(n4 + 255) / 256, 256>>>((const float4*)pred, n4);
    k_coarse<<<MAXB * NSEG, 256>>>(1);
    k_walk<<<MAXB, 256>>>(1, tgt);
    k_hist2<<<(n4 + 255) / 256, 256>>>((const float4*)pred, n4);
    k_coarse<<<MAXB * NSEG, 256>>>(2);
    k_walk<<<MAXB, 256>>>(2, tgt);

    int total4 = n * (C / 4);
    k_prune<<<(total4 + 255) / 256, 256>>>((const float4*)fea, pred,
                                           (float4*)d_out, out_keep,
                                           total4, writeKeep);
}

// round 5
// speedup vs baseline: 1.3521x; 1.0267x over previous
#include <cuda_runtime.h>
#include <cstdint>

// ---------------------------------------------------------------------------
// GenerativeUpsample: per-batch kth-smallest threshold on pred, prune fea.
//   fea:  [N, 64] f32   d_in[0]
//   pred: [N, 1]  f32   d_in[1]
//   bid:  [N]     i32   d_in[2]  (sorted)
//   tgt:  [B]     i32   d_in[3]
// out: [N*64] pruned fea, then (if room) [N] keep as 0/1 float.
//
// Exact 2-level (16+16 bit) radix select on monotone uint key of pred.
// 6 launches: bounds, hist1, select1, hist2, select2, prune(+hist re-zero).
// Hist arrays are zeroed at module load and re-zeroed by every prune call,
// so each invocation (correctness / capture / replay) starts clean.
// ---------------------------------------------------------------------------

#define MAXB 8
#define NBIN 65536

__device__ __align__(16) unsigned g_hist1[MAXB * NBIN];
__device__ __align__(16) unsigned g_hist2[MAXB * NBIN];
__device__ int      g_off[MAXB + 1];
__device__ unsigned g_selBin[MAXB];
__device__ unsigned g_selRank[MAXB];
__device__ int      g_active[MAXB];
__device__ unsigned g_threshKey[MAXB];

__device__ __forceinline__ unsigned f2key(float f) {
    unsigned u = __float_as_uint(f);
    return (u & 0x80000000u) ? ~u : (u | 0x80000000u);
}

__device__ __forceinline__ int batch_of(int i, const int* o) {
    int b = 0;
    #pragma unroll
    for (int k = 1; k < MAXB; k++) b += (i >= o[k]);
    return b;
}

// -------- batch boundaries via binary search (bids sorted) -----------------
__global__ void k_bounds(const int* __restrict__ bid, int n) {
    int t = threadIdx.x;
    if (t > MAXB) return;
    if (t == MAXB) { g_off[MAXB] = n; return; }
    int lo = 0, hi = n;
    while (lo < hi) {
        int mid = (lo + hi) >> 1;
        if (bid[mid] < t) lo = mid + 1; else hi = mid;
    }
    g_off[t] = lo;
}

// -------- pass 1: top-16-bit histogram, float4 loads -----------------------
__global__ void k_hist1(const float4* __restrict__ pred4, int n4) {
    __shared__ int soff[MAXB + 1];
    if (threadIdx.x <= MAXB) soff[threadIdx.x] = g_off[threadIdx.x];
    __syncthreads();
    int o[MAXB + 1];
    #pragma unroll
    for (int k = 0; k <= MAXB; k++) o[k] = soff[k];

    for (int i4 = blockIdx.x * blockDim.x + threadIdx.x; i4 < n4;
         i4 += gridDim.x * blockDim.x) {
        float4 p = pred4[i4];
        int base = i4 * 4;
        float pv[4] = {p.x, p.y, p.z, p.w};
        #pragma unroll
        for (int j = 0; j < 4; j++) {
            int b = batch_of(base + j, o);
            atomicAdd(&g_hist1[b * NBIN + (f2key(pv[j]) >> 16)], 1u);
        }
    }
}

// -------- pass 2: low-16-bit histogram of in-selected-bin elements ---------
__global__ void k_hist2(const float4* __restrict__ pred4, int n4) {
    __shared__ int soff[MAXB + 1];
    __shared__ unsigned ssel[MAXB];
    if (threadIdx.x <= MAXB) soff[threadIdx.x] = g_off[threadIdx.x];
    if (threadIdx.x < MAXB)  ssel[threadIdx.x] = g_selBin[threadIdx.x];
    __syncthreads();
    int o[MAXB + 1];
    #pragma unroll
    for (int k = 0; k <= MAXB; k++) o[k] = soff[k];

    for (int i4 = blockIdx.x * blockDim.x + threadIdx.x; i4 < n4;
         i4 += gridDim.x * blockDim.x) {
        float4 p = pred4[i4];
        int base = i4 * 4;
        float pv[4] = {p.x, p.y, p.z, p.w};
        #pragma unroll
        for (int j = 0; j < 4; j++) {
            int b = batch_of(base + j, o);
            unsigned key = f2key(pv[j]);
            if ((key >> 16) == ssel[b])
                atomicAdd(&g_hist2[b * NBIN + (key & 0xFFFFu)], 1u);
        }
    }
}

// -------- fused select: one block per batch, 1024 threads ------------------
// Thread t sums bins [t*64, t*64+64).  ssum[s] = sum over 16 group-sums.
// Staged walks happen in smem to avoid serial global-latency chains.
__global__ void k_select(int level, const int* __restrict__ tgt) {
    const unsigned* hist = (level == 1) ? g_hist1 : g_hist2;
    int b = blockIdx.x;
    __shared__ unsigned gsum[1024];
    __shared__ unsigned ssum[64];
    __shared__ unsigned sbin[64];
    __shared__ int sact;
    __shared__ long long srank;
    __shared__ int sgrp;

    const uint4* h4 = (const uint4*)&hist[b * NBIN];
    unsigned s = 0;
    int base = threadIdx.x * 16;
    #pragma unroll 4
    for (int j = 0; j < 16; j++) {
        uint4 v = h4[base + j];
        s += v.x + v.y + v.z + v.w;
    }
    gsum[threadIdx.x] = s;
    __syncthreads();
    if (threadIdx.x < 64) {
        unsigned t = 0;
        #pragma unroll 4
        for (int j = 0; j < 16; j++) t += gsum[threadIdx.x * 16 + j];
        ssum[threadIdx.x] = t;
    }
    __syncthreads();

    if (threadIdx.x == 0) {
        long long rank;
        int act;
        if (level == 1) {
            int nn = g_off[b + 1] - g_off[b];
            int t = tgt[b];
            act = (nn > t);
            rank = (long long)nn - t - 1;
        } else {
            act = g_active[b];
            rank = (long long)g_selRank[b];
        }
        sact = act;
        if (act) {
            int sg = 0;
            while (rank >= (long long)ssum[sg]) { rank -= ssum[sg]; sg++; }
            int g = sg * 16;
            while (rank >= (long long)gsum[g]) { rank -= gsum[g]; g++; }
            sgrp = g;
            srank = rank;
        }
    }
    __syncthreads();
    if (!sact) {
        if (threadIdx.x == 0) {
            if (level == 1) {
                g_active[b] = 0;
                g_selBin[b] = 0xFFFFFFFFu;  // matches nothing in pass 2
                g_selRank[b] = 0;
            } else {
                g_threshKey[b] = 0u;  // every real key > 0 -> keep all
            }
        }
        return;
    }
    if (threadIdx.x < 64) sbin[threadIdx.x] = hist[b * NBIN + sgrp * 64 + threadIdx.x];
    __syncthreads();
    if (threadIdx.x == 0) {
        long long rank = srank;
        int j = 0;
        while (rank >= (long long)sbin[j]) { rank -= sbin[j]; j++; }
        unsigned bin = (unsigned)(sgrp * 64 + j);
        if (level == 1) {
            g_selBin[b] = bin;
            g_selRank[b] = (unsigned)rank;
            g_active[b] = 1;
        } else {
            g_threshKey[b] = (g_selBin[b] << 16) | bin;
        }
    }
}

// -------- streaming prune: 2 x float4 per thread + hist re-zero ------------
__global__ void k_prune(const float4* __restrict__ fea4,
                        const float* __restrict__ pred,
                        float4* __restrict__ out4,
                        float* __restrict__ out_keep,
                        int total2, int writeKeep) {
    __shared__ unsigned sthr[MAXB];
    __shared__ int soff[MAXB + 1];
    if (threadIdx.x < MAXB) sthr[threadIdx.x] = g_threshKey[threadIdx.x];
    if (threadIdx.x >= 32 && threadIdx.x <= 32 + MAXB)
        soff[threadIdx.x - 32] = g_off[threadIdx.x - 32];
    __syncthreads();

    int gid = blockIdx.x * blockDim.x + threadIdx.x;

    // fold histogram re-zero for next invocation (graph replay determinism)
    {
        const int ZW = (MAXB * NBIN) / 4;  // uint4 words per hist = 131072
        if (gid < ZW) {
            uint4 z = make_uint4(0u, 0u, 0u, 0u);
            ((uint4*)g_hist1)[gid] = z;
        } else if (gid < 2 * ZW) {
            uint4 z = make_uint4(0u, 0u, 0u, 0u);
            ((uint4*)g_hist2)[gid - ZW] = z;
        }
    }

    if (gid >= total2) return;
    int row = gid >> 3;  // 8 threads per 64-wide row (2 float4 each)
    int o[MAXB + 1];
    #pragma unroll
    for (int k = 0; k <= MAXB; k++) o[k] = soff[k];
    int b = batch_of(row, o);
    unsigned key = f2key(pred[row]);
    float kf = (key > sthr[b]) ? 1.0f : 0.0f;
    float4 v0 = __ldcs(&fea4[2 * gid]);
    float4 v1 = __ldcs(&fea4[2 * gid + 1]);
    v0.x *= kf; v0.y *= kf; v0.z *= kf; v0.w *= kf;
    v1.x *= kf; v1.y *= kf; v1.z *= kf; v1.w *= kf;
    __stcs(&out4[2 * gid], v0);
    __stcs(&out4[2 * gid + 1], v1);
    if (writeKeep && ((gid & 7) == 0)) out_keep[row] = kf;
}

extern "C" void kernel_launch(void* const* d_in, const int* in_sizes, int n_in,
                              void* d_out, int out_size) {
    const float* fea  = (const float*)d_in[0];
    const float* pred = (const float*)d_in[1];
    const int*   bid  = (const int*)d_in[2];
    const int*   tgt  = (const int*)d_in[3];
    const int n = in_sizes[1];      // N points
    const int C = in_sizes[0] / n;  // 64

    float* out_fea  = (float*)d_out;
    int writeKeep = (out_size >= n * C + n) ? 1 : 0;
    float* out_keep = out_fea + (size_t)n * C;

    k_bounds<<<1, 32>>>(bid, n);
    int n4 = n / 4;
    k_hist1<<<(n4 + 255) / 256, 256>>>((const float4*)pred, n4);
    k_select<<<MAXB, 1024>>>(1, tgt);
    k_hist2<<<(n4 + 255) / 256, 256>>>((const float4*)pred, n4);
    k_select<<<MAXB, 1024>>>(2, tgt);

    int total2 = n * (C / 8);  // threads, 2 float4 each
    k_prune<<<(total2 + 511) / 512, 512>>>((const float4*)fea, pred,
                                           (float4*)d_out, out_keep,
                                           total2, writeKeep);
}

// round 6
// speedup vs baseline: 1.5184x; 1.1230x over previous
#include <cuda_runtime.h>
#include <cstdint>

// ---------------------------------------------------------------------------
// GenerativeUpsample: per-batch kth-smallest threshold on pred, prune fea.
//   fea:  [N, 64] f32   d_in[0]
//   pred: [N, 1]  f32   d_in[1]
//   bid:  [N]     i32   d_in[2]  (sorted)
//   tgt:  [B]     i32   d_in[3]
// out: [N*64] pruned fea, then (if room) [N] keep as 0/1 float.
//
// Exact 2-level (16+16 bit) radix select on monotone uint key of pred.
// Prune skips fea reads for dropped rows (output is zeros there) — cuts
// ~half the input stream traffic.
// ---------------------------------------------------------------------------

#define MAXB 8
#define NBIN 65536
#define NSEG 64
#define SEGBINS 1024

__device__ __align__(16) unsigned g_hist1[MAXB * NBIN];
__device__ __align__(16) unsigned g_hist2[MAXB * NBIN];
__device__ unsigned g_seg[MAXB * NSEG];
__device__ int      g_off[MAXB + 1];
__device__ unsigned g_selBin[MAXB];
__device__ unsigned g_selRank[MAXB];
__device__ int      g_active[MAXB];
__device__ unsigned g_threshKey[MAXB];

__device__ __forceinline__ unsigned f2key(float f) {
    unsigned u = __float_as_uint(f);
    return (u & 0x80000000u) ? ~u : (u | 0x80000000u);
}

__device__ __forceinline__ int batch_of(int i, const int* o) {
    int b = 0;
    #pragma unroll
    for (int k = 1; k < MAXB; k++) b += (i >= o[k]);
    return b;
}

// -------- batch boundaries via binary search (bids sorted) -----------------
__global__ void k_bounds(const int* __restrict__ bid, int n) {
    int t = threadIdx.x;
    if (t > MAXB) return;
    if (t == MAXB) { g_off[MAXB] = n; return; }
    int lo = 0, hi = n;
    while (lo < hi) {
        int mid = (lo + hi) >> 1;
        if (bid[mid] < t) lo = mid + 1; else hi = mid;
    }
    g_off[t] = lo;
}

// -------- pass 1: top-16-bit histogram, float4 loads -----------------------
__global__ void k_hist1(const float4* __restrict__ pred4, int n4) {
    __shared__ int soff[MAXB + 1];
    if (threadIdx.x <= MAXB) soff[threadIdx.x] = g_off[threadIdx.x];
    __syncthreads();
    int o[MAXB + 1];
    #pragma unroll
    for (int k = 0; k <= MAXB; k++) o[k] = soff[k];

    for (int i4 = blockIdx.x * blockDim.x + threadIdx.x; i4 < n4;
         i4 += gridDim.x * blockDim.x) {
        float4 p = pred4[i4];
        int base = i4 * 4;
        float pv[4] = {p.x, p.y, p.z, p.w};
        #pragma unroll
        for (int j = 0; j < 4; j++) {
            int b = batch_of(base + j, o);
            atomicAdd(&g_hist1[b * NBIN + (f2key(pv[j]) >> 16)], 1u);
        }
    }
}

// -------- pass 2: low-16-bit histogram of in-selected-bin elements ---------
__global__ void k_hist2(const float4* __restrict__ pred4, int n4) {
    __shared__ int soff[MAXB + 1];
    __shared__ unsigned ssel[MAXB];
    if (threadIdx.x <= MAXB) soff[threadIdx.x] = g_off[threadIdx.x];
    if (threadIdx.x < MAXB)  ssel[threadIdx.x] = g_selBin[threadIdx.x];
    __syncthreads();
    int o[MAXB + 1];
    #pragma unroll
    for (int k = 0; k <= MAXB; k++) o[k] = soff[k];

    for (int i4 = blockIdx.x * blockDim.x + threadIdx.x; i4 < n4;
         i4 += gridDim.x * blockDim.x) {
        float4 p = pred4[i4];
        int base = i4 * 4;
        float pv[4] = {p.x, p.y, p.z, p.w};
        #pragma unroll
        for (int j = 0; j < 4; j++) {
            int b = batch_of(base + j, o);
            unsigned key = f2key(pv[j]);
            if ((key >> 16) == ssel[b])
                atomicAdd(&g_hist2[b * NBIN + (key & 0xFFFFu)], 1u);
        }
    }
}

// -------- coarse segment sums: 8 batches x 64 segs = 512 blocks ------------
__global__ void k_coarse(int which) {
    const unsigned* hist = (which == 1) ? g_hist1 : g_hist2;
    int b = blockIdx.x >> 6;
    int s = blockIdx.x & 63;
    const uint4* h4 = (const uint4*)&hist[b * NBIN + s * SEGBINS];
    uint4 v = h4[threadIdx.x];
    unsigned sum = v.x + v.y + v.z + v.w;
    #pragma unroll
    for (int d = 16; d > 0; d >>= 1) sum += __shfl_down_sync(0xFFFFFFFFu, sum, d);
    __shared__ unsigned ws[8];
    if ((threadIdx.x & 31) == 0) ws[threadIdx.x >> 5] = sum;
    __syncthreads();
    if (threadIdx.x == 0) {
        unsigned t = 0;
        #pragma unroll
        for (int w = 0; w < 8; w++) t += ws[w];
        g_seg[b * NSEG + s] = t;
    }
}

// -------- walk: exact bin + residual rank, 8 tiny blocks -------------------
__global__ void k_walk(int level, const int* __restrict__ tgt) {
    const unsigned* hist = (level == 1) ? g_hist1 : g_hist2;
    int b = blockIdx.x;
    __shared__ unsigned ssum[256];
    __shared__ int sact;
    __shared__ unsigned srank, ssegi;

    if (threadIdx.x == 0) {
        long long rank;
        int act;
        if (level == 1) {
            int nn = g_off[b + 1] - g_off[b];
            int t = tgt[b];
            act = (nn > t);
            rank = (long long)nn - t - 1;
        } else {
            act = g_active[b];
            rank = (long long)g_selRank[b];
        }
        if (act) {
            const unsigned* seg = &g_seg[b * NSEG];
            int s = 0;
            while (rank >= (long long)seg[s]) { rank -= seg[s]; s++; }
            ssegi = (unsigned)s;
            srank = (unsigned)rank;
        }
        sact = act;
    }
    __syncthreads();
    if (!sact) {
        if (threadIdx.x == 0) {
            if (level == 1) {
                g_active[b] = 0;
                g_selBin[b] = 0xFFFFFFFFu;  // matches nothing in pass 2
                g_selRank[b] = 0;
            } else {
                g_threshKey[b] = 0u;  // every real key > 0 -> keep all
            }
        }
        return;
    }
    const uint4* h4 = (const uint4*)&hist[b * NBIN + ssegi * SEGBINS];
    uint4 v = h4[threadIdx.x];
    ssum[threadIdx.x] = v.x + v.y + v.z + v.w;
    __syncthreads();
    if (threadIdx.x == 0) {
        long long rank = (long long)srank;
        int tt = 0;
        while (rank >= (long long)ssum[tt]) { rank -= ssum[tt]; tt++; }
        const unsigned* hb = &hist[b * NBIN + ssegi * SEGBINS + tt * 4];
        int j = 0;
        while (rank >= (long long)hb[j]) { rank -= hb[j]; j++; }
        unsigned bin = ssegi * SEGBINS + tt * 4 + j;
        if (level == 1) {
            g_selBin[b] = bin;
            g_selRank[b] = (unsigned)rank;
            g_active[b] = 1;
        } else {
            g_threshKey[b] = (g_selBin[b] << 16) | bin;
        }
    }
}

// -------- streaming prune: skip fea reads for dropped rows -----------------
__global__ void k_prune(const float4* __restrict__ fea4,
                        const float* __restrict__ pred,
                        float4* __restrict__ out4,
                        float* __restrict__ out_keep,
                        int total2, int writeKeep) {
    __shared__ unsigned sthr[MAXB];
    __shared__ int soff[MAXB + 1];
    if (threadIdx.x < MAXB) sthr[threadIdx.x] = g_threshKey[threadIdx.x];
    if (threadIdx.x >= 32 && threadIdx.x <= 32 + MAXB)
        soff[threadIdx.x - 32] = g_off[threadIdx.x - 32];
    __syncthreads();

    int gid = blockIdx.x * blockDim.x + threadIdx.x;

    // fold histogram re-zero for next invocation (graph replay determinism)
    {
        const int ZW = (MAXB * NBIN) / 4;  // uint4 words per hist
        if (gid < ZW) {
            ((uint4*)g_hist1)[gid] = make_uint4(0u, 0u, 0u, 0u);
        } else if (gid < 2 * ZW) {
            ((uint4*)g_hist2)[gid - ZW] = make_uint4(0u, 0u, 0u, 0u);
        }
    }

    if (gid >= total2) return;
    int row = gid >> 3;  // 8 threads per 64-wide row (2 float4 each)
    int o[MAXB + 1];
    #pragma unroll
    for (int k = 0; k <= MAXB; k++) o[k] = soff[k];
    int b = batch_of(row, o);
    unsigned key = f2key(pred[row]);
    bool keep = key > sthr[b];

    float4 v0 = make_float4(0.f, 0.f, 0.f, 0.f);
    float4 v1 = v0;
    if (keep) {  // dropped rows: no fea read at all (output is zeros)
        v0 = __ldcs(&fea4[2 * gid]);
        v1 = __ldcs(&fea4[2 * gid + 1]);
    }
    __stcs(&out4[2 * gid], v0);
    __stcs(&out4[2 * gid + 1], v1);
    if (writeKeep && ((gid & 7) == 0)) out_keep[row] = keep ? 1.0f : 0.0f;
}

extern "C" void kernel_launch(void* const* d_in, const int* in_sizes, int n_in,
                              void* d_out, int out_size) {
    const float* fea  = (const float*)d_in[0];
    const float* pred = (const float*)d_in[1];
    const int*   bid  = (const int*)d_in[2];
    const int*   tgt  = (const int*)d_in[3];
    const int n = in_sizes[1];      // N points
    const int C = in_sizes[0] / n;  // 64

    float* out_fea  = (float*)d_out;
    int writeKeep = (out_size >= n * C + n) ? 1 : 0;
    float* out_keep = out_fea + (size_t)n * C;

    k_bounds<<<1, 32>>>(bid, n);
    int n4 = n / 4;
    k_hist1<<<(n4 + 255) / 256, 256>>>((const float4*)pred, n4);
    k_coarse<<<MAXB * NSEG, 256>>>(1);
    k_walk<<<MAXB, 256>>>(1, tgt);
    k_hist2<<<(n4 + 255) / 256, 256>>>((const float4*)pred, n4);
    k_coarse<<<MAXB * NSEG, 256>>>(2);
    k_walk<<<MAXB, 256>>>(2, tgt);

    int total2 = n * (C / 8);  // threads, 2 float4 each
    k_prune<<<(total2 + 511) / 512, 512>>>((const float4*)fea, pred,
                                           (float4*)d_out, out_keep,
                                           total2, writeKeep);
}

// round 7
// speedup vs baseline: 1.6360x; 1.0775x over previous
#include <cuda_runtime.h>
#include <cstdint>

// ---------------------------------------------------------------------------
// GenerativeUpsample: per-batch kth-smallest threshold on pred, prune fea.
//   fea:  [N, 64] f32   d_in[0]
//   pred: [N, 1]  f32   d_in[1]
//   bid:  [N]     i32   d_in[2]  (sorted)
//   tgt:  [B]     i32   d_in[3]
// out: [N*64] pruned fea, then (if room) [N] keep as 0/1 float.
//
// Exact 2-level (16+16 bit) radix select on monotone uint key of pred.
// Walk kernels use parallel prefix-scan selection (no serial latency chains).
// Prune skips fea reads for dropped rows.
// ---------------------------------------------------------------------------

#define MAXB 8
#define NBIN 65536
#define NSEG 64
#define SEGBINS 1024

__device__ __align__(16) unsigned g_hist1[MAXB * NBIN];
__device__ __align__(16) unsigned g_hist2[MAXB * NBIN];
__device__ unsigned g_seg[MAXB * NSEG];
__device__ int      g_off[MAXB + 1];
__device__ unsigned g_selBin[MAXB];
__device__ unsigned g_selRank[MAXB];
__device__ int      g_active[MAXB];
__device__ unsigned g_threshKey[MAXB];

__device__ __forceinline__ unsigned f2key(float f) {
    unsigned u = __float_as_uint(f);
    return (u & 0x80000000u) ? ~u : (u | 0x80000000u);
}

__device__ __forceinline__ int batch_of(int i, const int* o) {
    int b = 0;
    #pragma unroll
    for (int k = 1; k < MAXB; k++) b += (i >= o[k]);
    return b;
}

// block-wide (256 thr) exclusive scan; wsum is an 8-word smem scratch.
// Contains __syncthreads; caller must sync before reusing wsum.
__device__ __forceinline__ unsigned scan_excl(unsigned val, int tid,
                                              unsigned* wsum) {
    int lane = tid & 31, wid = tid >> 5;
    unsigned x = val;
    #pragma unroll
    for (int d = 1; d < 32; d <<= 1) {
        unsigned y = __shfl_up_sync(0xFFFFFFFFu, x, d);
        if (lane >= d) x += y;
    }
    if (lane == 31) wsum[wid] = x;
    __syncthreads();
    if (tid == 0) {
        unsigned a = 0;
        #pragma unroll
        for (int w = 0; w < 8; w++) { unsigned t = wsum[w]; wsum[w] = a; a += t; }
    }
    __syncthreads();
    return wsum[wid] + x - val;  // exclusive prefix
}

// -------- batch boundaries via binary search (bids sorted) -----------------
__global__ void k_bounds(const int* __restrict__ bid, int n) {
    int t = threadIdx.x;
    if (t > MAXB) return;
    if (t == MAXB) { g_off[MAXB] = n; return; }
    int lo = 0, hi = n;
    while (lo < hi) {
        int mid = (lo + hi) >> 1;
        if (bid[mid] < t) lo = mid + 1; else hi = mid;
    }
    g_off[t] = lo;
}

// -------- pass 1: top-16-bit histogram, float4 loads -----------------------
__global__ void k_hist1(const float4* __restrict__ pred4, int n4) {
    __shared__ int soff[MAXB + 1];
    if (threadIdx.x <= MAXB) soff[threadIdx.x] = g_off[threadIdx.x];
    __syncthreads();
    int o[MAXB + 1];
    #pragma unroll
    for (int k = 0; k <= MAXB; k++) o[k] = soff[k];

    for (int i4 = blockIdx.x * blockDim.x + threadIdx.x; i4 < n4;
         i4 += gridDim.x * blockDim.x) {
        float4 p = pred4[i4];
        int base = i4 * 4;
        float pv[4] = {p.x, p.y, p.z, p.w};
        #pragma unroll
        for (int j = 0; j < 4; j++) {
            int b = batch_of(base + j, o);
            atomicAdd(&g_hist1[b * NBIN + (f2key(pv[j]) >> 16)], 1u);
        }
    }
}

// -------- pass 2: low-16-bit histogram of in-selected-bin elements ---------
__global__ void k_hist2(const float4* __restrict__ pred4, int n4) {
    __shared__ int soff[MAXB + 1];
    __shared__ unsigned ssel[MAXB];
    if (threadIdx.x <= MAXB) soff[threadIdx.x] = g_off[threadIdx.x];
    if (threadIdx.x < MAXB)  ssel[threadIdx.x] = g_selBin[threadIdx.x];
    __syncthreads();
    int o[MAXB + 1];
    #pragma unroll
    for (int k = 0; k <= MAXB; k++) o[k] = soff[k];

    for (int i4 = blockIdx.x * blockDim.x + threadIdx.x; i4 < n4;
         i4 += gridDim.x * blockDim.x) {
        float4 p = pred4[i4];
        int base = i4 * 4;
        float pv[4] = {p.x, p.y, p.z, p.w};
        #pragma unroll
        for (int j = 0; j < 4; j++) {
            int b = batch_of(base + j, o);
            unsigned key = f2key(pv[j]);
            if ((key >> 16) == ssel[b])
                atomicAdd(&g_hist2[b * NBIN + (key & 0xFFFFu)], 1u);
        }
    }
}

// -------- coarse segment sums: 8 batches x 64 segs = 512 blocks ------------
__global__ void k_coarse(int which) {
    const unsigned* hist = (which == 1) ? g_hist1 : g_hist2;
    int b = blockIdx.x >> 6;
    int s = blockIdx.x & 63;
    const uint4* h4 = (const uint4*)&hist[b * NBIN + s * SEGBINS];
    uint4 v = h4[threadIdx.x];
    unsigned sum = v.x + v.y + v.z + v.w;
    #pragma unroll
    for (int d = 16; d > 0; d >>= 1) sum += __shfl_down_sync(0xFFFFFFFFu, sum, d);
    __shared__ unsigned ws[8];
    if ((threadIdx.x & 31) == 0) ws[threadIdx.x >> 5] = sum;
    __syncthreads();
    if (threadIdx.x == 0) {
        unsigned t = 0;
        #pragma unroll
        for (int w = 0; w < 8; w++) t += ws[w];
        g_seg[b * NSEG + s] = t;
    }
}

// -------- walk: parallel scan-based selection, 8 blocks x 256 thr ----------
__global__ void k_walk(int level, const int* __restrict__ tgt) {
    const unsigned* hist = (level == 1) ? g_hist1 : g_hist2;
    int b = blockIdx.x;
    int tid = threadIdx.x;
    __shared__ unsigned wsum[8];
    __shared__ int sact;
    __shared__ unsigned srank;
    __shared__ int ssegi;
    __shared__ unsigned srank2;

    if (tid == 0) {
        long long rank;
        int act;
        if (level == 1) {
            int nn = g_off[b + 1] - g_off[b];
            int t = tgt[b];
            act = (nn > t);
            rank = (long long)nn - t - 1;
        } else {
            act = g_active[b];
            rank = (long long)g_selRank[b];
        }
        sact = act;
        srank = (unsigned)rank;
    }
    __syncthreads();
    if (!sact) {
        if (tid == 0) {
            if (level == 1) {
                g_active[b] = 0;
                g_selBin[b] = 0xFFFFFFFFu;  // matches nothing in pass 2
                g_selRank[b] = 0;
            } else {
                g_threshKey[b] = 0u;  // every real key > 0 -> keep all
            }
        }
        return;
    }

    // level A: pick segment among 64 seg-sums (parallel, scan-select)
    unsigned v = (tid < NSEG) ? g_seg[b * NSEG + tid] : 0u;
    unsigned e = scan_excl(v, tid, wsum);
    unsigned r = srank;
    if (r >= e && r < e + v) { ssegi = tid; srank2 = r - e; }
    __syncthreads();

    // level B: pick bin among 1024 bins of the segment (4 per thread)
    const uint4* h4 = (const uint4*)&hist[b * NBIN + ssegi * SEGBINS];
    uint4 q = h4[tid];
    unsigned v2 = q.x + q.y + q.z + q.w;
    unsigned e2 = scan_excl(v2, tid, wsum);
    unsigned r2 = srank2;
    if (r2 >= e2 && r2 < e2 + v2) {
        unsigned rr = r2 - e2;
        unsigned bvals[4] = {q.x, q.y, q.z, q.w};
        int j = 0;
        while (rr >= bvals[j]) { rr -= bvals[j]; j++; }
        unsigned bin = (unsigned)(ssegi * SEGBINS + tid * 4 + j);
        if (level == 1) {
            g_selBin[b] = bin;
            g_selRank[b] = rr;
            g_active[b] = 1;
        } else {
            g_threshKey[b] = (g_selBin[b] << 16) | bin;
        }
    }
}

// -------- streaming prune: skip fea reads for dropped rows -----------------
__global__ void k_prune(const float4* __restrict__ fea4,
                        const float* __restrict__ pred,
                        float4* __restrict__ out4,
                        float* __restrict__ out_keep,
                        int total2, int writeKeep) {
    __shared__ unsigned sthr[MAXB];
    __shared__ int soff[MAXB + 1];
    if (threadIdx.x < MAXB) sthr[threadIdx.x] = g_threshKey[threadIdx.x];
    if (threadIdx.x >= 32 && threadIdx.x <= 32 + MAXB)
        soff[threadIdx.x - 32] = g_off[threadIdx.x - 32];
    __syncthreads();

    int gid = blockIdx.x * blockDim.x + threadIdx.x;

    // fold histogram re-zero for next invocation (graph replay determinism)
    {
        const int ZW = (MAXB * NBIN) / 4;  // uint4 words per hist
        if (gid < ZW) {
            ((uint4*)g_hist1)[gid] = make_uint4(0u, 0u, 0u, 0u);
        } else if (gid < 2 * ZW) {
            ((uint4*)g_hist2)[gid - ZW] = make_uint4(0u, 0u, 0u, 0u);
        }
    }

    if (gid >= total2) return;
    int row = gid >> 3;  // 8 threads per 64-wide row (2 float4 each)
    int o[MAXB + 1];
    #pragma unroll
    for (int k = 0; k <= MAXB; k++) o[k] = soff[k];
    int b = batch_of(row, o);
    unsigned key = f2key(pred[row]);
    bool keep = key > sthr[b];

    float4 v0 = make_float4(0.f, 0.f, 0.f, 0.f);
    float4 v1 = v0;
    if (keep) {  // dropped rows: no fea read (output is zeros there)
        v0 = __ldcs(&fea4[2 * gid]);
        v1 = __ldcs(&fea4[2 * gid + 1]);
    }
    __stcs(&out4[2 * gid], v0);
    __stcs(&out4[2 * gid + 1], v1);
    if (writeKeep && ((gid & 7) == 0)) out_keep[row] = keep ? 1.0f : 0.0f;
}

extern "C" void kernel_launch(void* const* d_in, const int* in_sizes, int n_in,
                              void* d_out, int out_size) {
    const float* fea  = (const float*)d_in[0];
    const float* pred = (const float*)d_in[1];
    const int*   bid  = (const int*)d_in[2];
    const int*   tgt  = (const int*)d_in[3];
    const int n = in_sizes[1];      // N points
    const int C = in_sizes[0] / n;  // 64

    float* out_fea  = (float*)d_out;
    int writeKeep = (out_size >= n * C + n) ? 1 : 0;
    float* out_keep = out_fea + (size_t)n * C;

    k_bounds<<<1, 32>>>(bid, n);
    int n4 = n / 4;
    k_hist1<<<(n4 + 255) / 256, 256>>>((const float4*)pred, n4);
    k_coarse<<<MAXB * NSEG, 256>>>(1);
    k_walk<<<MAXB, 256>>>(1, tgt);
    k_hist2<<<(n4 + 255) / 256, 256>>>((const float4*)pred, n4);
    k_coarse<<<MAXB * NSEG, 256>>>(2);
    k_walk<<<MAXB, 256>>>(2, tgt);

    int total2 = n * (C / 8);  // threads, 2 float4 each
    k_prune<<<(total2 + 511) / 512, 512>>>((const float4*)fea, pred,
                                           (float4*)d_out, out_keep,
                                           total2, writeKeep);
}